// round 9
// baseline (speedup 1.0000x reference)
#include <cuda_runtime.h>
#include <cuda_fp16.h>
#include <cstdint>

#define T_TOK 8192
#define DIM 1024
#define NEXP 16
#define TOPK 2
#define INTER 2048
#define ATOT (T_TOK * TOPK)

#define BM 128
#define BK 32
#define STAGES 4
#define APITCH 40                       // halves; 80B rows, conflict-free ldsm
#define BTPITCH 40                      // halves; B^T rows (32 k + 8 pad)
#define A_ST_HALVES (BM * APITCH)       // 5120
#define BT_ST_HALVES (256 * BTPITCH)    // 10240 (256 n-rows per stage)
#define DSMEM_SZ (STAGES * (A_ST_HALVES + BT_ST_HALVES) * 2)   // 122880 B

// ---------------- scratch (static device globals; no allocation) ----------------
__device__ __half g_xh[(size_t)T_TOK * DIM];          // 16 MB
__device__ __half g_Hh[(size_t)ATOT * INTER];         // 67 MB
__device__ __half g_W1t[(size_t)NEXP * INTER * DIM];  // 67 MB  [E][N][K]
__device__ __half g_W3t[(size_t)NEXP * INTER * DIM];  // 67 MB
__device__ __half g_W2t[(size_t)NEXP * DIM * INTER];  // 67 MB  [E][N][K]
__device__ __half g_Yp[(size_t)ATOT * DIM];           // 33.5 MB
__device__ int   g_ti[ATOT];
__device__ float g_tw[ATOT];
__device__ int   g_counts[NEXP];    // BSS-zero initially; re-zeroed by k_combine
__device__ int   g_offsets[NEXP];
__device__ int   g_cursor[NEXP];
__device__ int   g_tok[ATOT];
__device__ float g_w[ATOT];
__device__ int   g_pos[ATOT];

// ---------------- helpers ----------------
__device__ __forceinline__ uint32_t su32(const void* p) {
    return (uint32_t)__cvta_generic_to_shared(p);
}
__device__ __forceinline__ void ldsm4(uint32_t addr, unsigned* r) {
    asm volatile("ldmatrix.sync.aligned.m8n8.x4.shared.b16 {%0,%1,%2,%3}, [%4];"
                 : "=r"(r[0]), "=r"(r[1]), "=r"(r[2]), "=r"(r[3]) : "r"(addr));
}
__device__ __forceinline__ void mma16(float* c, const unsigned* a, unsigned b0, unsigned b1) {
    asm volatile(
        "mma.sync.aligned.m16n8k16.row.col.f32.f16.f16.f32 "
        "{%0,%1,%2,%3},{%4,%5,%6,%7},{%8,%9},{%0,%1,%2,%3};"
        : "+f"(c[0]), "+f"(c[1]), "+f"(c[2]), "+f"(c[3])
        : "r"(a[0]), "r"(a[1]), "r"(a[2]), "r"(a[3]), "r"(b0), "r"(b1));
}
__device__ __forceinline__ void cpa16(uint32_t saddr, const void* g) {
    asm volatile("cp.async.cg.shared.global [%0], [%1], 16;" :: "r"(saddr), "l"(g));
}
#define CP_COMMIT asm volatile("cp.async.commit_group;" ::: "memory")
#define CP_WAIT2  asm volatile("cp.async.wait_group 2;" ::: "memory")

__device__ __forceinline__ float silu_f(float v) {
    return v * (1.f / (1.f + __expf(-v)));
}

// ---------------- weight transpose+convert: [R][C] fp32 -> [C][R] fp16 ----------------
__global__ __launch_bounds__(256) void k_tr(const float* __restrict__ src,
                                            __half* __restrict__ dst, int R, int C) {
    __shared__ __half tile[32][33];
    const int e = blockIdx.z;
    const int c0 = blockIdx.x * 32, r0 = blockIdx.y * 32;
    const float* s = src + (size_t)e * R * C;
    __half* d = dst + (size_t)e * R * C;
#pragma unroll
    for (int i = 0; i < 4; i++) {
        const int r = r0 + threadIdx.y + i * 8;
        tile[threadIdx.x][threadIdx.y + i * 8] = __float2half(s[(size_t)r * C + c0 + threadIdx.x]);
    }
    __syncthreads();
#pragma unroll
    for (int i = 0; i < 4; i++) {
        const int c = c0 + threadIdx.y + i * 8;
        d[(size_t)c * R + r0 + threadIdx.x] = tile[threadIdx.y + i * 8][threadIdx.x];
    }
}

// ---------------- gate (+ x fp16 conversion fused) ----------------
__global__ __launch_bounds__(256) void k_gate(const float* __restrict__ x,
                                              const float* __restrict__ Wg,
                                              const float* __restrict__ bg) {
    const int warp = threadIdx.x >> 5, lane = threadIdx.x & 31;
    const int t = blockIdx.x * 8 + warp;
    if (t >= T_TOK) return;
    float acc[NEXP];
#pragma unroll
    for (int e = 0; e < NEXP; e++) acc[e] = 0.f;
    const float* xr = x + (size_t)t * DIM;
    __half* xh = g_xh + (size_t)t * DIM;
#pragma unroll 4
    for (int i = 0; i < DIM / 32; i++) {
        const int d = i * 32 + lane;
        const float xv = xr[d];
        xh[d] = __float2half(xv);
        const float4* wr = reinterpret_cast<const float4*>(Wg + (size_t)d * NEXP);
        float4 w0 = wr[0], w1 = wr[1], w2 = wr[2], w3 = wr[3];
        acc[0] += xv * w0.x;  acc[1] += xv * w0.y;  acc[2] += xv * w0.z;  acc[3] += xv * w0.w;
        acc[4] += xv * w1.x;  acc[5] += xv * w1.y;  acc[6] += xv * w1.z;  acc[7] += xv * w1.w;
        acc[8] += xv * w2.x;  acc[9] += xv * w2.y;  acc[10] += xv * w2.z; acc[11] += xv * w2.w;
        acc[12] += xv * w3.x; acc[13] += xv * w3.y; acc[14] += xv * w3.z; acc[15] += xv * w3.w;
    }
#pragma unroll
    for (int e = 0; e < NEXP; e++) {
        float v = acc[e];
#pragma unroll
        for (int o = 16; o > 0; o >>= 1) v += __shfl_xor_sync(0xffffffffu, v, o);
        acc[e] = v + bg[e];
    }
    float mx = acc[0];
#pragma unroll
    for (int e = 1; e < NEXP; e++) mx = fmaxf(mx, acc[e]);
    float p[NEXP];
#pragma unroll
    for (int e = 0; e < NEXP; e++) p[e] = __expf(acc[e] - mx);
    int i0, i1; float p0, p1;
    if (p[0] >= p[1]) { i0 = 0; p0 = p[0]; i1 = 1; p1 = p[1]; }
    else              { i0 = 1; p0 = p[1]; i1 = 0; p1 = p[0]; }
#pragma unroll
    for (int e = 2; e < NEXP; e++) {
        if (p[e] > p0)      { i1 = i0; p1 = p0; i0 = e; p0 = p[e]; }
        else if (p[e] > p1) { i1 = e; p1 = p[e]; }
    }
    if (lane == 0) {
        const float ws = p0 + p1;
        g_ti[2 * t] = i0;     g_tw[2 * t] = p0 / ws;
        g_ti[2 * t + 1] = i1; g_tw[2 * t + 1] = p1 / ws;
        atomicAdd(&g_counts[i0], 1);
        atomicAdd(&g_counts[i1], 1);
    }
}

__global__ void k_prefix() {
    int s = 0;
    for (int e = 0; e < NEXP; e++) { g_offsets[e] = s; s += g_counts[e]; }
}
__global__ void k_scatter() {
    const int t = blockIdx.x * blockDim.x + threadIdx.x;
    if (t >= T_TOK) return;
#pragma unroll
    for (int k = 0; k < TOPK; k++) {
        const int e = g_ti[2 * t + k];
        const int slot = atomicAdd(&g_cursor[e], 1);
        const int pos = g_offsets[e] + slot;
        g_tok[pos] = t;
        g_w[pos] = g_tw[2 * t + k];
        g_pos[2 * t + k] = pos;
    }
}

// ---------------- fused GLU GEMM: H = silu(xW1+b1)*(xW3+b3) ----------------
// 512 threads, tile 128 x (128+128), BK=32, 4-stage pipeline; B^T n-major (no trans ldsm)
__global__ __launch_bounds__(512, 1) void k_glu(const float* __restrict__ b1,
                                                const float* __restrict__ b3) {
    const int e = blockIdx.z;
    const int cnt = g_counts[e];
    const int mt = blockIdx.x;
    if (mt * BM >= cnt) return;
    const int nt = blockIdx.y;     // 0..15 (128 cols per matrix)
    const int seg = g_offsets[e];
    const int tid = threadIdx.x;
    const int wid = tid >> 5, lane = tid & 31;

    extern __shared__ __half sm[];
    __half* As = sm;                               // [STAGES][128][APITCH]
    __half* Bs = sm + STAGES * A_ST_HALVES;        // [STAGES][256][BTPITCH]

    // A loader: one 16B seg per thread
    const int aRow = tid >> 2;
    const int aoff = (tid & 3) * 8;
    const int grow = mt * BM + aRow;
    const int prow = seg + ((grow < cnt) ? grow : (cnt - 1));
    const __half* aptr = g_xh + (size_t)g_tok[prow] * DIM + aoff;

    // B loader: 256 n-rows x 32 k halves; thread -> row tid>>1, 2 segs
    const int brow = tid >> 1;            // 0..255
    const int bo = (tid & 1) * 16;        // 0 or 16 halves
    const __half* wsrc = (brow < 128)
        ? g_W1t + ((size_t)e * INTER + nt * 128 + brow) * DIM + bo
        : g_W3t + ((size_t)e * INTER + nt * 128 + (brow - 128)) * DIM + bo;
    const int bdst = brow * BTPITCH + bo;

    const int wm = wid & 3, wn = wid >> 2;   // 4m x 4n; warp tile 32 rows x (32+32) cols
    const int alrow = lane & 15, aseg = (lane >> 4) * 8;
    const int bnoff = (lane & 7) | ((lane >> 1) & 8);   // 0..15 n-row within frag
    const int bkoff = lane & 8;                          // 0 or 8 k-col
    const int g = lane >> 2, tg = lane & 3;

    float acc1[2][4][4], acc3[2][4][4];
#pragma unroll
    for (int i = 0; i < 2; i++)
#pragma unroll
        for (int j = 0; j < 4; j++)
#pragma unroll
            for (int q = 0; q < 4; q++) { acc1[i][j][q] = 0.f; acc3[i][j][q] = 0.f; }

#pragma unroll
    for (int c = 0; c < STAGES - 1; c++) {
        cpa16(su32(As + (size_t)c * A_ST_HALVES + aRow * APITCH + aoff), aptr + c * BK);
        __half* Bd = Bs + (size_t)c * BT_ST_HALVES + bdst;
        cpa16(su32(Bd), wsrc + c * BK);
        cpa16(su32(Bd + 8), wsrc + c * BK + 8);
        CP_COMMIT;
    }

    const int NKT = DIM / BK;  // 32
#pragma unroll 1
    for (int j = 0; j < NKT; j++) {
        CP_WAIT2;
        __syncthreads();
        const int nc = j + STAGES - 1;
        if (nc < NKT) {
            const int ns = nc & 3;
            cpa16(su32(As + (size_t)ns * A_ST_HALVES + aRow * APITCH + aoff), aptr + nc * BK);
            __half* Bd = Bs + (size_t)ns * BT_ST_HALVES + bdst;
            cpa16(su32(Bd), wsrc + nc * BK);
            cpa16(su32(Bd + 8), wsrc + nc * BK + 8);
        }
        CP_COMMIT;

        const __half* Ab = As + (size_t)(j & 3) * A_ST_HALVES;
        const __half* Bb = Bs + (size_t)(j & 3) * BT_ST_HALVES;
#pragma unroll
        for (int ks = 0; ks < 2; ks++) {
            unsigned af[2][4];
#pragma unroll
            for (int mi = 0; mi < 2; mi++)
                ldsm4(su32(&Ab[(wm * 32 + mi * 16 + alrow) * APITCH + ks * 16 + aseg]), af[mi]);
#pragma unroll
            for (int nh = 0; nh < 2; nh++) {
                unsigned bf[4];
                ldsm4(su32(&Bb[(wn * 32 + nh * 16 + bnoff) * BTPITCH + ks * 16 + bkoff]), bf);
#pragma unroll
                for (int mi = 0; mi < 2; mi++) {
                    mma16(acc1[mi][2 * nh],     af[mi], bf[0], bf[1]);
                    mma16(acc1[mi][2 * nh + 1], af[mi], bf[2], bf[3]);
                }
            }
#pragma unroll
            for (int nh = 0; nh < 2; nh++) {
                unsigned bf[4];
                ldsm4(su32(&Bb[(128 + wn * 32 + nh * 16 + bnoff) * BTPITCH + ks * 16 + bkoff]), bf);
#pragma unroll
                for (int mi = 0; mi < 2; mi++) {
                    mma16(acc3[mi][2 * nh],     af[mi], bf[0], bf[1]);
                    mma16(acc3[mi][2 * nh + 1], af[mi], bf[2], bf[3]);
                }
            }
        }
    }

    // epilogue: h = silu(v1+b1)*(v3+b3) -> fp16
#pragma unroll
    for (int mi = 0; mi < 2; mi++) {
        const int rl0 = mt * BM + wm * 32 + mi * 16 + g;
        const int rl1 = rl0 + 8;
#pragma unroll
        for (int ni = 0; ni < 4; ni++) {
            const int col = nt * 128 + wn * 32 + ni * 8 + 2 * tg;
            const float bb1x = b1[e * INTER + col], bb1y = b1[e * INTER + col + 1];
            const float bb3x = b3[e * INTER + col], bb3y = b3[e * INTER + col + 1];
            if (rl0 < cnt) {
                const float h0 = silu_f(acc1[mi][ni][0] + bb1x) * (acc3[mi][ni][0] + bb3x);
                const float h1 = silu_f(acc1[mi][ni][1] + bb1y) * (acc3[mi][ni][1] + bb3y);
                *reinterpret_cast<__half2*>(&g_Hh[(size_t)(seg + rl0) * INTER + col]) = __floats2half2_rn(h0, h1);
            }
            if (rl1 < cnt) {
                const float h0 = silu_f(acc1[mi][ni][2] + bb1x) * (acc3[mi][ni][2] + bb3x);
                const float h1 = silu_f(acc1[mi][ni][3] + bb1y) * (acc3[mi][ni][3] + bb3y);
                *reinterpret_cast<__half2*>(&g_Hh[(size_t)(seg + rl1) * INTER + col]) = __floats2half2_rn(h0, h1);
            }
        }
    }
}

// ---------------- down GEMM: Yp = (H@W2 + b2) * w  (fp16 out) ----------------
// 512 threads, tile 128 x 256, BK=32, 4-stage pipeline; B^T n-major
__global__ __launch_bounds__(512, 1) void k_down(const float* __restrict__ b2) {
    const int e = blockIdx.z;
    const int cnt = g_counts[e];
    const int mt = blockIdx.x;
    if (mt * BM >= cnt) return;
    const int nt = blockIdx.y;     // 0..3
    const int seg = g_offsets[e];
    const int tid = threadIdx.x;
    const int wid = tid >> 5, lane = tid & 31;

    extern __shared__ __half sm[];
    __half* As = sm;
    __half* Bs = sm + STAGES * A_ST_HALVES;

    const int aRow = tid >> 2;
    const int aoff = (tid & 3) * 8;
    int ar = seg + mt * BM + aRow;
    if (ar > ATOT - 1) ar = ATOT - 1;
    const __half* aptr = g_Hh + (size_t)ar * INTER + aoff;

    const int brow = tid >> 1;            // 0..255
    const int bo = (tid & 1) * 16;
    const __half* wsrc = g_W2t + ((size_t)e * DIM + nt * 256 + brow) * INTER + bo;
    const int bdst = brow * BTPITCH + bo;

    const int wm = wid & 3, wn = wid >> 2;   // 4m x 4n; warp tile 32 x 64
    const int alrow = lane & 15, aseg = (lane >> 4) * 8;
    const int bnoff = (lane & 7) | ((lane >> 1) & 8);
    const int bkoff = lane & 8;
    const int g = lane >> 2, tg = lane & 3;

    float acc[2][8][4];
#pragma unroll
    for (int i = 0; i < 2; i++)
#pragma unroll
        for (int j = 0; j < 8; j++)
#pragma unroll
            for (int q = 0; q < 4; q++) acc[i][j][q] = 0.f;

#pragma unroll
    for (int c = 0; c < STAGES - 1; c++) {
        cpa16(su32(As + (size_t)c * A_ST_HALVES + aRow * APITCH + aoff), aptr + c * BK);
        __half* Bd = Bs + (size_t)c * BT_ST_HALVES + bdst;
        cpa16(su32(Bd), wsrc + c * BK);
        cpa16(su32(Bd + 8), wsrc + c * BK + 8);
        CP_COMMIT;
    }

    const int NKT = INTER / BK;  // 64
#pragma unroll 1
    for (int j = 0; j < NKT; j++) {
        CP_WAIT2;
        __syncthreads();
        const int nc = j + STAGES - 1;
        if (nc < NKT) {
            const int ns = nc & 3;
            cpa16(su32(As + (size_t)ns * A_ST_HALVES + aRow * APITCH + aoff), aptr + nc * BK);
            __half* Bd = Bs + (size_t)ns * BT_ST_HALVES + bdst;
            cpa16(su32(Bd), wsrc + nc * BK);
            cpa16(su32(Bd + 8), wsrc + nc * BK + 8);
        }
        CP_COMMIT;

        const __half* Ab = As + (size_t)(j & 3) * A_ST_HALVES;
        const __half* Bb = Bs + (size_t)(j & 3) * BT_ST_HALVES;
#pragma unroll
        for (int ks = 0; ks < 2; ks++) {
            unsigned af[2][4];
#pragma unroll
            for (int mi = 0; mi < 2; mi++)
                ldsm4(su32(&Ab[(wm * 32 + mi * 16 + alrow) * APITCH + ks * 16 + aseg]), af[mi]);
#pragma unroll
            for (int nh = 0; nh < 4; nh++) {
                unsigned bf[4];
                ldsm4(su32(&Bb[(wn * 64 + nh * 16 + bnoff) * BTPITCH + ks * 16 + bkoff]), bf);
#pragma unroll
                for (int mi = 0; mi < 2; mi++) {
                    mma16(acc[mi][2 * nh],     af[mi], bf[0], bf[1]);
                    mma16(acc[mi][2 * nh + 1], af[mi], bf[2], bf[3]);
                }
            }
        }
    }

    // epilogue: weighted fp16 positional write
#pragma unroll
    for (int mi = 0; mi < 2; mi++) {
        const int rl0 = mt * BM + wm * 32 + mi * 16 + g;
        const int rl1 = rl0 + 8;
        const int p0 = seg + rl0, p1 = seg + rl1;
        const float w0 = (rl0 < cnt) ? g_w[p0] : 0.f;
        const float w1 = (rl1 < cnt) ? g_w[p1] : 0.f;
#pragma unroll
        for (int ni = 0; ni < 8; ni++) {
            const int col = nt * 256 + wn * 64 + ni * 8 + 2 * tg;
            const float bbx = b2[e * DIM + col], bby = b2[e * DIM + col + 1];
            if (rl0 < cnt)
                *reinterpret_cast<__half2*>(&g_Yp[(size_t)p0 * DIM + col]) =
                    __floats2half2_rn((acc[mi][ni][0] + bbx) * w0, (acc[mi][ni][1] + bby) * w0);
            if (rl1 < cnt)
                *reinterpret_cast<__half2*>(&g_Yp[(size_t)p1 * DIM + col]) =
                    __floats2half2_rn((acc[mi][ni][2] + bbx) * w1, (acc[mi][ni][3] + bby) * w1);
        }
    }
}

// ---------------- combine: y[t] = Yp[p0] + Yp[p1]; re-zero counters ----------------
__global__ void k_combine(float* __restrict__ y) {
    const int idx = blockIdx.x * blockDim.x + threadIdx.x;
    if (idx < NEXP) { g_counts[idx] = 0; g_cursor[idx] = 0; }
    const int n4 = T_TOK * DIM / 4;
    if (idx >= n4) return;
    const int t = idx / (DIM / 4);
    const int c4 = idx % (DIM / 4);
    const int p0 = g_pos[2 * t], p1 = g_pos[2 * t + 1];
    const __half2* ra = reinterpret_cast<const __half2*>(&g_Yp[(size_t)p0 * DIM + 4 * c4]);
    const __half2* rb = reinterpret_cast<const __half2*>(&g_Yp[(size_t)p1 * DIM + 4 * c4]);
    const float2 a0 = __half22float2(ra[0]), a1 = __half22float2(ra[1]);
    const float2 b0 = __half22float2(rb[0]), b1 = __half22float2(rb[1]);
    reinterpret_cast<float4*>(y)[idx] =
        make_float4(a0.x + b0.x, a0.y + b0.y, a1.x + b1.x, a1.y + b1.y);
}

// ---------------- launch ----------------
extern "C" void kernel_launch(void* const* d_in, const int* in_sizes, int n_in,
                              void* d_out, int out_size) {
    const float* x  = (const float*)d_in[0];
    const float* Wg = (const float*)d_in[1];
    const float* bg = (const float*)d_in[2];
    const float* W1 = (const float*)d_in[3];
    const float* b1 = (const float*)d_in[4];
    const float* W2 = (const float*)d_in[5];
    const float* b2 = (const float*)d_in[6];
    const float* W3 = (const float*)d_in[7];
    const float* b3 = (const float*)d_in[8];
    float* y = (float*)d_out;

    cudaFuncSetAttribute(k_glu,  cudaFuncAttributeMaxDynamicSharedMemorySize, DSMEM_SZ);
    cudaFuncSetAttribute(k_down, cudaFuncAttributeMaxDynamicSharedMemorySize, DSMEM_SZ);

    __half* w1t; cudaGetSymbolAddress((void**)&w1t, g_W1t);
    __half* w3t; cudaGetSymbolAddress((void**)&w3t, g_W3t);
    __half* w2t; cudaGetSymbolAddress((void**)&w2t, g_W2t);
    dim3 trb(32, 8);
    k_tr<<<dim3(INTER / 32, DIM / 32, NEXP), trb>>>(W1, w1t, DIM, INTER);   // [K][N]->[N][K]
    k_tr<<<dim3(INTER / 32, DIM / 32, NEXP), trb>>>(W3, w3t, DIM, INTER);
    k_tr<<<dim3(DIM / 32, INTER / 32, NEXP), trb>>>(W2, w2t, INTER, DIM);

    k_gate<<<T_TOK / 8, 256>>>(x, Wg, bg);
    k_prefix<<<1, 1>>>();
    k_scatter<<<(T_TOK + 255) / 256, 256>>>();

    dim3 gglu(T_TOK / BM, INTER / 128, NEXP);    // (64, 16, 16), mt fastest
    k_glu<<<gglu, 512, DSMEM_SZ>>>(b1, b3);

    dim3 gdown(T_TOK / BM, DIM / 256, NEXP);     // (64, 4, 16)
    k_down<<<gdown, 512, DSMEM_SZ>>>(b2);

    const int n4 = T_TOK * DIM / 4;
    k_combine<<<(n4 + 255) / 256, 256>>>(y);
}

// round 10
// speedup vs baseline: 1.2244x; 1.2244x over previous
#include <cuda_runtime.h>
#include <cuda_fp16.h>
#include <cstdint>

#define T_TOK 8192
#define DIM 1024
#define NEXP 16
#define TOPK 2
#define INTER 2048
#define ATOT (T_TOK * TOPK)

#define BM 128
#define BNG 128        // glu: cols per weight matrix (W1 + W3 share the B tile)
#define BND 256        // down: output cols per CTA
#define BK 32
#define STAGES 4
#define APITCH 40      // halves; 80B rows
#define BPITCH 264     // halves; 528B rows
#define A_ST_HALVES (BM * APITCH)       // 5120
#define B_ST_HALVES (BK * BPITCH)       // 8448
#define DSMEM_SZ (STAGES * (A_ST_HALVES + B_ST_HALVES) * 2)   // 108544 B
#define GATE_SMEM (DIM * 17 * 4)        // 69632 B

// ---------------- scratch (static device globals; no allocation) ----------------
__device__ __half g_xh[(size_t)T_TOK * DIM];          // 16 MB
__device__ __half g_Hh[(size_t)ATOT * INTER];         // 67 MB
__device__ __half g_W1h[(size_t)NEXP * DIM * INTER];  // 67 MB  [E][K][N]
__device__ __half g_W3h[(size_t)NEXP * DIM * INTER];  // 67 MB
__device__ __half g_W2h[(size_t)NEXP * INTER * DIM];  // 67 MB
__device__ __half g_Yp[(size_t)ATOT * DIM];           // 33.5 MB
__device__ int   g_ti[ATOT];
__device__ float g_tw[ATOT];
__device__ int   g_counts[NEXP];    // BSS-zero initially; re-zeroed by k_combine
__device__ int   g_offsets[NEXP];
__device__ int   g_cursor[NEXP];
__device__ int   g_tok[ATOT];
__device__ float g_w[ATOT];
__device__ int   g_pos[ATOT];

// ---------------- helpers ----------------
__device__ __forceinline__ uint32_t su32(const void* p) {
    return (uint32_t)__cvta_generic_to_shared(p);
}
__device__ __forceinline__ void ldsm4(uint32_t addr, unsigned* r) {
    asm volatile("ldmatrix.sync.aligned.m8n8.x4.shared.b16 {%0,%1,%2,%3}, [%4];"
                 : "=r"(r[0]), "=r"(r[1]), "=r"(r[2]), "=r"(r[3]) : "r"(addr));
}
__device__ __forceinline__ void ldsm4t(uint32_t addr, unsigned* r) {
    asm volatile("ldmatrix.sync.aligned.m8n8.x4.trans.shared.b16 {%0,%1,%2,%3}, [%4];"
                 : "=r"(r[0]), "=r"(r[1]), "=r"(r[2]), "=r"(r[3]) : "r"(addr));
}
__device__ __forceinline__ void mma16(float* c, const unsigned* a, unsigned b0, unsigned b1) {
    asm volatile(
        "mma.sync.aligned.m16n8k16.row.col.f32.f16.f16.f32 "
        "{%0,%1,%2,%3},{%4,%5,%6,%7},{%8,%9},{%0,%1,%2,%3};"
        : "+f"(c[0]), "+f"(c[1]), "+f"(c[2]), "+f"(c[3])
        : "r"(a[0]), "r"(a[1]), "r"(a[2]), "r"(a[3]), "r"(b0), "r"(b1));
}
__device__ __forceinline__ void cpa16(uint32_t saddr, const void* g) {
    asm volatile("cp.async.cg.shared.global [%0], [%1], 16;" :: "r"(saddr), "l"(g));
}
#define CP_COMMIT asm volatile("cp.async.commit_group;" ::: "memory")
#define CP_WAIT2  asm volatile("cp.async.wait_group 2;" ::: "memory")

__device__ __forceinline__ uint4 pack8(float4 a, float4 b) {
    uint4 u;
    __half2 h;
    h = __floats2half2_rn(a.x, a.y); u.x = *(unsigned*)&h;
    h = __floats2half2_rn(a.z, a.w); u.y = *(unsigned*)&h;
    h = __floats2half2_rn(b.x, b.y); u.z = *(unsigned*)&h;
    h = __floats2half2_rn(b.z, b.w); u.w = *(unsigned*)&h;
    return u;
}
__device__ __forceinline__ float silu_f(float v) {
    return v * (1.f / (1.f + __expf(-v)));
}

// ---------------- fused weight conversion (W1|W3|W2 by blockIdx.y) ----------------
__global__ __launch_bounds__(256) void k_wconv3(const float* __restrict__ W1,
                                                const float* __restrict__ W3,
                                                const float* __restrict__ W2) {
    const float* src = (blockIdx.y == 0) ? W1 : (blockIdx.y == 1) ? W3 : W2;
    __half* dst = (blockIdx.y == 0) ? g_W1h : (blockIdx.y == 1) ? g_W3h : g_W2h;
    const size_t n16 = (size_t)NEXP * DIM * INTER / 16;
    const size_t stride = (size_t)gridDim.x * blockDim.x;
    for (size_t i = (size_t)blockIdx.x * blockDim.x + threadIdx.x; i < n16; i += stride) {
        const float4* s = reinterpret_cast<const float4*>(src) + 4 * i;
        float4 a = s[0], b = s[1], c = s[2], d = s[3];
        uint4* o = reinterpret_cast<uint4*>(dst) + 2 * i;
        o[0] = pack8(a, b);
        o[1] = pack8(c, d);
    }
}

// ---------------- gate: smem-cached Wg, fused x->fp16 ----------------
__global__ __launch_bounds__(256) void k_gate(const float* __restrict__ x,
                                              const float* __restrict__ Wg,
                                              const float* __restrict__ bg) {
    extern __shared__ float sWg[];   // [DIM][17] padded
    const int tid = threadIdx.x;
    for (int idx = tid; idx < DIM * NEXP; idx += 256) {
        const int d = idx >> 4, e = idx & 15;
        sWg[d * 17 + e] = Wg[idx];
    }
    __syncthreads();

    const int warp = tid >> 5, lane = tid & 31;
    const int t = blockIdx.x * 8 + warp;
    if (t >= T_TOK) return;

    float acc[NEXP];
#pragma unroll
    for (int e = 0; e < NEXP; e++) acc[e] = 0.f;
    const float* xr = x + (size_t)t * DIM;
    __half* xh = g_xh + (size_t)t * DIM;
#pragma unroll 4
    for (int i = 0; i < DIM / 32; i++) {
        const int d = i * 32 + lane;
        const float xv = xr[d];
        xh[d] = __float2half(xv);
        const float* wr = &sWg[d * 17];
#pragma unroll
        for (int e = 0; e < NEXP; e++) acc[e] += xv * wr[e];
    }
#pragma unroll
    for (int e = 0; e < NEXP; e++) {
        float v = acc[e];
#pragma unroll
        for (int o = 16; o > 0; o >>= 1) v += __shfl_xor_sync(0xffffffffu, v, o);
        acc[e] = v + bg[e];
    }
    float mx = acc[0];
#pragma unroll
    for (int e = 1; e < NEXP; e++) mx = fmaxf(mx, acc[e]);
    float p[NEXP];
#pragma unroll
    for (int e = 0; e < NEXP; e++) p[e] = __expf(acc[e] - mx);
    int i0, i1; float p0, p1;
    if (p[0] >= p[1]) { i0 = 0; p0 = p[0]; i1 = 1; p1 = p[1]; }
    else              { i0 = 1; p0 = p[1]; i1 = 0; p1 = p[0]; }
#pragma unroll
    for (int e = 2; e < NEXP; e++) {
        if (p[e] > p0)      { i1 = i0; p1 = p0; i0 = e; p0 = p[e]; }
        else if (p[e] > p1) { i1 = e; p1 = p[e]; }
    }
    if (lane == 0) {
        const float ws = p0 + p1;
        g_ti[2 * t] = i0;     g_tw[2 * t] = p0 / ws;
        g_ti[2 * t + 1] = i1; g_tw[2 * t + 1] = p1 / ws;
        atomicAdd(&g_counts[i0], 1);
        atomicAdd(&g_counts[i1], 1);
    }
}

__global__ void k_prefix() {
    int s = 0;
    for (int e = 0; e < NEXP; e++) { g_offsets[e] = s; s += g_counts[e]; }
}
__global__ void k_scatter() {
    const int t = blockIdx.x * blockDim.x + threadIdx.x;
    if (t >= T_TOK) return;
#pragma unroll
    for (int k = 0; k < TOPK; k++) {
        const int e = g_ti[2 * t + k];
        const int slot = atomicAdd(&g_cursor[e], 1);
        const int pos = g_offsets[e] + slot;
        g_tok[pos] = t;
        g_w[pos] = g_tw[2 * t + k];
        g_pos[2 * t + k] = pos;
    }
}

// ---------------- fused GLU GEMM: H = silu(xW1+b1)*(xW3+b3) ----------------
// R4 structure verbatim: 512 threads, tile 128 x (128+128), BK=32, 4-stage cp.async
__global__ __launch_bounds__(512, 1) void k_glu(const float* __restrict__ b1,
                                                const float* __restrict__ b3) {
    const int e = blockIdx.z;
    const int cnt = g_counts[e];
    const int mt = blockIdx.x;
    if (mt * BM >= cnt) return;
    const int nt = blockIdx.y;
    const int seg = g_offsets[e];
    const int tid = threadIdx.x;
    const int wid = tid >> 5, lane = tid & 31;

    extern __shared__ __half sm[];
    __half* As = sm;                              // [STAGES][BM][APITCH]
    __half* Bs = sm + STAGES * A_ST_HALVES;       // [STAGES][BK][BPITCH]

    const int aRow = tid >> 2;
    const int aSeg = (tid & 3) * 8;
    const int grow = mt * BM + aRow;
    const int prow = seg + ((grow < cnt) ? grow : (cnt - 1));
    const __half* aptr = g_xh + (size_t)g_tok[prow] * DIM + aSeg;

    const int bK = tid >> 4;           // 0..31
    const int bSeg = (tid & 15) * 8;   // 0..120 halves
    const __half* w1p = g_W1h + (size_t)e * DIM * INTER + (size_t)bK * INTER + nt * BNG + bSeg;
    const __half* w3p = g_W3h + (size_t)e * DIM * INTER + (size_t)bK * INTER + nt * BNG + bSeg;

    const int wm = wid & 3, wn = wid >> 2;   // 4m x 4n
    const int lrow = lane & 15, lseg = (lane >> 4) * 8;
    const int g = lane >> 2, tg = lane & 3;

    float acc1[2][4][4], acc3[2][4][4];
#pragma unroll
    for (int i = 0; i < 2; i++)
#pragma unroll
        for (int j = 0; j < 4; j++)
#pragma unroll
            for (int q = 0; q < 4; q++) { acc1[i][j][q] = 0.f; acc3[i][j][q] = 0.f; }

#pragma unroll
    for (int c = 0; c < STAGES - 1; c++) {
        cpa16(su32(&As[(size_t)c * A_ST_HALVES + aRow * APITCH + aSeg]), aptr + c * BK);
        cpa16(su32(&Bs[(size_t)c * B_ST_HALVES + bK * BPITCH + bSeg]), w1p + (size_t)c * BK * INTER);
        cpa16(su32(&Bs[(size_t)c * B_ST_HALVES + bK * BPITCH + 128 + bSeg]), w3p + (size_t)c * BK * INTER);
        CP_COMMIT;
    }

    const int NKT = DIM / BK;  // 32
#pragma unroll 1
    for (int j = 0; j < NKT; j++) {
        CP_WAIT2;
        __syncthreads();
        const int st = j & (STAGES - 1);
        const __half* Ab = As + (size_t)st * A_ST_HALVES;
        const __half* Bb = Bs + (size_t)st * B_ST_HALVES;
#pragma unroll
        for (int ks = 0; ks < 2; ks++) {
            unsigned af[2][4];
#pragma unroll
            for (int mi = 0; mi < 2; mi++)
                ldsm4(su32(&Ab[(wm * 32 + mi * 16 + lrow) * APITCH + ks * 16 + lseg]), af[mi]);
#pragma unroll
            for (int nh = 0; nh < 2; nh++) {
                unsigned bf[4];
                ldsm4t(su32(&Bb[(ks * 16 + lrow) * BPITCH + wn * 32 + nh * 16 + lseg]), bf);
#pragma unroll
                for (int mi = 0; mi < 2; mi++) {
                    mma16(acc1[mi][2 * nh],     af[mi], bf[0], bf[1]);
                    mma16(acc1[mi][2 * nh + 1], af[mi], bf[2], bf[3]);
                }
            }
#pragma unroll
            for (int nh = 0; nh < 2; nh++) {
                unsigned bf[4];
                ldsm4t(su32(&Bb[(ks * 16 + lrow) * BPITCH + 128 + wn * 32 + nh * 16 + lseg]), bf);
#pragma unroll
                for (int mi = 0; mi < 2; mi++) {
                    mma16(acc3[mi][2 * nh],     af[mi], bf[0], bf[1]);
                    mma16(acc3[mi][2 * nh + 1], af[mi], bf[2], bf[3]);
                }
            }
        }
        const int nc = j + STAGES - 1;
        if (nc < NKT) {
            const int ns = nc & (STAGES - 1);
            cpa16(su32(&As[(size_t)ns * A_ST_HALVES + aRow * APITCH + aSeg]), aptr + nc * BK);
            cpa16(su32(&Bs[(size_t)ns * B_ST_HALVES + bK * BPITCH + bSeg]), w1p + (size_t)nc * BK * INTER);
            cpa16(su32(&Bs[(size_t)ns * B_ST_HALVES + bK * BPITCH + 128 + bSeg]), w3p + (size_t)nc * BK * INTER);
        }
        CP_COMMIT;
    }

    // epilogue: h = silu(v1+b1)*(v3+b3) -> fp16
#pragma unroll
    for (int mi = 0; mi < 2; mi++) {
        const int rl0 = mt * BM + wm * 32 + mi * 16 + g;
        const int rl1 = rl0 + 8;
#pragma unroll
        for (int ni = 0; ni < 4; ni++) {
            const int col = nt * BNG + wn * 32 + ni * 8 + 2 * tg;
            const float bb1x = b1[e * INTER + col], bb1y = b1[e * INTER + col + 1];
            const float bb3x = b3[e * INTER + col], bb3y = b3[e * INTER + col + 1];
            if (rl0 < cnt) {
                const float h0 = silu_f(acc1[mi][ni][0] + bb1x) * (acc3[mi][ni][0] + bb3x);
                const float h1 = silu_f(acc1[mi][ni][1] + bb1y) * (acc3[mi][ni][1] + bb3y);
                *reinterpret_cast<__half2*>(&g_Hh[(size_t)(seg + rl0) * INTER + col]) = __floats2half2_rn(h0, h1);
            }
            if (rl1 < cnt) {
                const float h0 = silu_f(acc1[mi][ni][2] + bb1x) * (acc3[mi][ni][2] + bb3x);
                const float h1 = silu_f(acc1[mi][ni][3] + bb1y) * (acc3[mi][ni][3] + bb3y);
                *reinterpret_cast<__half2*>(&g_Hh[(size_t)(seg + rl1) * INTER + col]) = __floats2half2_rn(h0, h1);
            }
        }
    }
}

// ---------------- down GEMM: Yp = (H@W2 + b2) * w  (fp16 out) ----------------
// R4 structure verbatim: 512 threads, tile 128 x 256, BK=32, 4-stage pipeline
__global__ __launch_bounds__(512, 1) void k_down(const float* __restrict__ b2) {
    const int e = blockIdx.z;
    const int cnt = g_counts[e];
    const int mt = blockIdx.x;
    if (mt * BM >= cnt) return;
    const int nt = blockIdx.y;
    const int seg = g_offsets[e];
    const int tid = threadIdx.x;
    const int wid = tid >> 5, lane = tid & 31;

    extern __shared__ __half sm[];
    __half* As = sm;
    __half* Bs = sm + STAGES * A_ST_HALVES;

    const int aRow = tid >> 2;
    const int aSeg = (tid & 3) * 8;
    int ar = seg + mt * BM + aRow;
    if (ar > ATOT - 1) ar = ATOT - 1;
    const __half* aptr = g_Hh + (size_t)ar * INTER + aSeg;

    const int bK = tid >> 4;
    const int bSeg = (tid & 15) * 8;
    const __half* w2p = g_W2h + (size_t)e * INTER * DIM + (size_t)bK * DIM + nt * BND + bSeg;

    const int wm = wid & 3, wn = wid >> 2;   // warp tile 32x64
    const int lrow = lane & 15, lseg = (lane >> 4) * 8;
    const int g = lane >> 2, tg = lane & 3;

    float acc[2][8][4];
#pragma unroll
    for (int i = 0; i < 2; i++)
#pragma unroll
        for (int j = 0; j < 8; j++)
#pragma unroll
            for (int q = 0; q < 4; q++) acc[i][j][q] = 0.f;

#pragma unroll
    for (int c = 0; c < STAGES - 1; c++) {
        cpa16(su32(&As[(size_t)c * A_ST_HALVES + aRow * APITCH + aSeg]), aptr + c * BK);
        cpa16(su32(&Bs[(size_t)c * B_ST_HALVES + bK * BPITCH + bSeg]), w2p + (size_t)c * BK * DIM);
        cpa16(su32(&Bs[(size_t)c * B_ST_HALVES + bK * BPITCH + 128 + bSeg]), w2p + 128 + (size_t)c * BK * DIM);
        CP_COMMIT;
    }

    const int NKT = INTER / BK;  // 64
#pragma unroll 1
    for (int j = 0; j < NKT; j++) {
        CP_WAIT2;
        __syncthreads();
        const int st = j & (STAGES - 1);
        const __half* Ab = As + (size_t)st * A_ST_HALVES;
        const __half* Bb = Bs + (size_t)st * B_ST_HALVES;
#pragma unroll
        for (int ks = 0; ks < 2; ks++) {
            unsigned af[2][4];
#pragma unroll
            for (int mi = 0; mi < 2; mi++)
                ldsm4(su32(&Ab[(wm * 32 + mi * 16 + lrow) * APITCH + ks * 16 + lseg]), af[mi]);
#pragma unroll
            for (int nh = 0; nh < 4; nh++) {
                unsigned bf[4];
                ldsm4t(su32(&Bb[(ks * 16 + lrow) * BPITCH + wn * 64 + nh * 16 + lseg]), bf);
#pragma unroll
                for (int mi = 0; mi < 2; mi++) {
                    mma16(acc[mi][2 * nh],     af[mi], bf[0], bf[1]);
                    mma16(acc[mi][2 * nh + 1], af[mi], bf[2], bf[3]);
                }
            }
        }
        const int nc = j + STAGES - 1;
        if (nc < NKT) {
            const int ns = nc & (STAGES - 1);
            cpa16(su32(&As[(size_t)ns * A_ST_HALVES + aRow * APITCH + aSeg]), aptr + nc * BK);
            cpa16(su32(&Bs[(size_t)ns * B_ST_HALVES + bK * BPITCH + bSeg]), w2p + (size_t)nc * BK * DIM);
            cpa16(su32(&Bs[(size_t)ns * B_ST_HALVES + bK * BPITCH + 128 + bSeg]), w2p + 128 + (size_t)nc * BK * DIM);
        }
        CP_COMMIT;
    }

    // epilogue: weighted fp16 positional write
#pragma unroll
    for (int mi = 0; mi < 2; mi++) {
        const int rl0 = mt * BM + wm * 32 + mi * 16 + g;
        const int rl1 = rl0 + 8;
        const int p0 = seg + rl0, p1 = seg + rl1;
        const float w0 = (rl0 < cnt) ? g_w[p0] : 0.f;
        const float w1 = (rl1 < cnt) ? g_w[p1] : 0.f;
#pragma unroll
        for (int ni = 0; ni < 8; ni++) {
            const int col = nt * BND + wn * 64 + ni * 8 + 2 * tg;
            const float bbx = b2[e * DIM + col], bby = b2[e * DIM + col + 1];
            if (rl0 < cnt)
                *reinterpret_cast<__half2*>(&g_Yp[(size_t)p0 * DIM + col]) =
                    __floats2half2_rn((acc[mi][ni][0] + bbx) * w0, (acc[mi][ni][1] + bby) * w0);
            if (rl1 < cnt)
                *reinterpret_cast<__half2*>(&g_Yp[(size_t)p1 * DIM + col]) =
                    __floats2half2_rn((acc[mi][ni][2] + bbx) * w1, (acc[mi][ni][3] + bby) * w1);
        }
    }
}

// ---------------- combine: y[t] = Yp[p0] + Yp[p1]; re-zero counters ----------------
__global__ void k_combine(float* __restrict__ y) {
    const int idx = blockIdx.x * blockDim.x + threadIdx.x;
    if (idx < NEXP) { g_counts[idx] = 0; g_cursor[idx] = 0; }
    const int n4 = T_TOK * DIM / 4;
    if (idx >= n4) return;
    const int t = idx / (DIM / 4);
    const int c4 = idx % (DIM / 4);
    const int p0 = g_pos[2 * t], p1 = g_pos[2 * t + 1];
    const __half2* ra = reinterpret_cast<const __half2*>(&g_Yp[(size_t)p0 * DIM + 4 * c4]);
    const __half2* rb = reinterpret_cast<const __half2*>(&g_Yp[(size_t)p1 * DIM + 4 * c4]);
    const float2 a0 = __half22float2(ra[0]), a1 = __half22float2(ra[1]);
    const float2 b0 = __half22float2(rb[0]), b1 = __half22float2(rb[1]);
    reinterpret_cast<float4*>(y)[idx] =
        make_float4(a0.x + b0.x, a0.y + b0.y, a1.x + b1.x, a1.y + b1.y);
}

// ---------------- launch ----------------
extern "C" void kernel_launch(void* const* d_in, const int* in_sizes, int n_in,
                              void* d_out, int out_size) {
    const float* x  = (const float*)d_in[0];
    const float* Wg = (const float*)d_in[1];
    const float* bg = (const float*)d_in[2];
    const float* W1 = (const float*)d_in[3];
    const float* b1 = (const float*)d_in[4];
    const float* W2 = (const float*)d_in[5];
    const float* b2 = (const float*)d_in[6];
    const float* W3 = (const float*)d_in[7];
    const float* b3 = (const float*)d_in[8];
    float* y = (float*)d_out;

    cudaFuncSetAttribute(k_glu,  cudaFuncAttributeMaxDynamicSharedMemorySize, DSMEM_SZ);
    cudaFuncSetAttribute(k_down, cudaFuncAttributeMaxDynamicSharedMemorySize, DSMEM_SZ);
    cudaFuncSetAttribute(k_gate, cudaFuncAttributeMaxDynamicSharedMemorySize, GATE_SMEM);

    k_wconv3<<<dim3(2048, 3), 256>>>(W1, W3, W2);
    k_gate<<<T_TOK / 8, 256, GATE_SMEM>>>(x, Wg, bg);
    k_prefix<<<1, 1>>>();
    k_scatter<<<(T_TOK + 255) / 256, 256>>>();

    dim3 gglu(T_TOK / BM, INTER / BNG, NEXP);    // (64, 16, 16), mt fastest
    k_glu<<<gglu, 512, DSMEM_SZ>>>(b1, b3);

    dim3 gdown(T_TOK / BM, DIM / BND, NEXP);     // (64, 4, 16)
    k_down<<<gdown, 512, DSMEM_SZ>>>(b2);

    const int n4 = T_TOK * DIM / 4;
    k_combine<<<(n4 + 255) / 256, 256>>>(y);
}